// round 10
// baseline (speedup 1.0000x reference)
#include <cuda_runtime.h>
#include <cuda_bf16.h>
#include <cstdint>

#define BATCH 8
#define CFULL 512
#define CI    256
#define LQ    4096
#define LK    2048

#define SWZ(x) ((x) ^ (((x) >> 3) & 0x70))

__device__ __forceinline__ uint32_t smem_u32(const void* p) {
    uint32_t a;
    asm("{ .reg .u64 t; cvta.to.shared.u64 t, %1; cvt.u32.u64 %0, t; }" : "=r"(a) : "l"(p));
    return a;
}

#define CPA(saddr, gptr) \
    asm volatile("cp.async.cg.shared.global [%0], [%1], 16;" :: "r"(saddr), "l"(gptr))
#define CP_COMMIT() asm volatile("cp.async.commit_group;" ::: "memory")
#define CP_WAIT1()  asm volatile("cp.async.wait_group 1;" ::: "memory")

#define LDSM4(r0, r1, r2, r3, addr) \
    asm volatile("ldmatrix.sync.aligned.m8n8.x4.shared.b16 {%0,%1,%2,%3}, [%4];" \
        : "=r"(r0), "=r"(r1), "=r"(r2), "=r"(r3) : "r"(addr))

#define MMA16816(d, a0, a1, a2, a3, b0, b1) \
    asm volatile("mma.sync.aligned.m16n8k16.row.col.f32.bf16.bf16.f32 " \
        "{%0,%1,%2,%3}, {%4,%5,%6,%7}, {%8,%9}, {%0,%1,%2,%3};" \
        : "+f"((d)[0]), "+f"((d)[1]), "+f"((d)[2]), "+f"((d)[3]) \
        : "r"(a0), "r"(a1), "r"(a2), "r"(a3), "r"(b0), "r"(b1))

// --------------------------------------------------------------- scratch
__device__ __nv_bfloat16 g_xt    [(size_t)BATCH * LQ * 1024];     // xT split [B][L][2C]
__device__ __nv_bfloat16 g_thetaT[(size_t)BATCH * LQ * 512];      // [B][L][2Ci]
__device__ __nv_bfloat16 g_phiPT [(size_t)BATCH * LK * 512];      // [B][L/2][2Ci]
__device__ __nv_bfloat16 g_gP    [(size_t)BATCH * CI * 4096];     // [B][Ci][2*L/2] split
__device__ __nv_bfloat16 g_fs    [(size_t)BATCH * LQ * 4096];     // exp(f) split
__device__ float         g_psum  [(size_t)BATCH * LQ * 32];       // partial row sums
__device__ float         g_inv   [(size_t)BATCH * LQ];            // 1/rowsum
__device__ __nv_bfloat16 g_yT    [(size_t)BATCH * LQ * 512];      // [B][L][2Ci]
__device__ float         g_z     [(size_t)BATCH * CFULL * LQ];    // [B][C][L]
__device__ float         g_bns   [(size_t)CFULL * 512];           // BN partial sums
__device__ float         g_bnq   [(size_t)CFULL * 512];           // BN partial sumsq
__device__ __nv_bfloat16 g_wth   [CI * 1024];
__device__ __nv_bfloat16 g_wph   [CI * 1024];
__device__ __nv_bfloat16 g_wg    [CI * 1024];
__device__ __nv_bfloat16 g_wwz   [CFULL * 512];
__device__ float g_mean[CFULL];
__device__ float g_var [CFULL];

// --------------------------------------------------------------- HMMA GEMM
// D[M,N] = sum over 3 split terms of A*B^T: (Ahi,Bhi),(Ahi,Blo),(Alo,Bhi).
// CTA tile 128x128, 128 threads, 4 warps (2m x 2n), warp tile 64x64,
// BK=64, 3-stage cp.async, register-double-buffered fragments.
#define SM_BYTES 98304
template<int BIASM, int BIASN, int SPLIT, int POOLM, int POOLN, int SOFTEXP, int SCALEM,
         int BNSTAT>
__global__ __launch_bounds__(128, 2)
void mma_gemm(const __nv_bfloat16* __restrict__ A, const __nv_bfloat16* __restrict__ B,
              const float* __restrict__ bias, const float* __restrict__ scalev,
              float* __restrict__ psum, float* __restrict__ psumq,
              void* __restrict__ Cv,
              int K, int lda, int ldb, int ldc, int lo_off,
              long sA, long sB, long sC)
{
    extern __shared__ char smem[];
    const uint32_t sb = smem_u32(smem);
    const int tid = threadIdx.x;
    const int wid = tid >> 5;
    const int lane = tid & 31;
    const int bm = blockIdx.y * 128;
    const int bn = blockIdx.x * 128;
    A += (long)blockIdx.z * sA;
    B += (long)blockIdx.z * sB;

    // loader: thread covers rows r0, r0+16, ..., r0+112 at col chunk c0 (16B)
    const int r0 = tid >> 3;
    const int c0 = tid & 7;
    const __nv_bfloat16* agp0 = A + (long)(bm + r0) * lda + c0 * 8;
    const __nv_bfloat16* bgp0 = B + (long)(bn + r0) * ldb + c0 * 8;
    const uint32_t asw0 = SWZ((uint32_t)(r0 * 128 + c0 * 16));          // +i*2048
    const long astep = 16L * lda;
    const long bstep = 16L * ldb;

    const int wm = wid >> 1;        // 0..1
    const int wn = wid & 1;         // 0..1
    uint32_t abase[4], bbase[4];
    #pragma unroll
    for (int mi = 0; mi < 4; mi++) {
        int arow = wm * 64 + mi * 16 + (lane & 15);
        abase[mi] = (uint32_t)(arow * 128) + ((((lane >> 4) << 4)) ^ ((arow & 7) << 4));
    }
    #pragma unroll
    for (int j2 = 0; j2 < 4; j2++) {
        int brow = wn * 64 + j2 * 16 + (lane & 7) + ((lane >> 4) << 3);
        uint32_t bcol = ((lane >> 3) & 1) << 4;
        bbase[j2] = 16384u + (uint32_t)(brow * 128) + (bcol ^ ((brow & 7) << 4));
    }

    float acc[4][8][4];
    #pragma unroll
    for (int i = 0; i < 4; i++)
        #pragma unroll
        for (int j = 0; j < 8; j++)
            #pragma unroll
            for (int q = 0; q < 4; q++)
                acc[i][j][q] = 0.f;

    const int kper = K >> 6;
    const int nIt = 3 * kper;

    auto offs = [&](int n, long& ao, long& bo) {
        int term = n / kper;
        int kk = (n - term * kper) << 6;
        ao = ((term == 2) ? (long)K : 0L) + kk;
        bo = ((term == 1) ? (long)K : 0L) + kk;
    };

    {   // prologue: stages 0 and 1
        long ao, bo;
        offs(0, ao, bo);
        #pragma unroll
        for (int i = 0; i < 8; i++) CPA(sb + asw0 + i * 2048u, agp0 + ao + i * astep);
        #pragma unroll
        for (int i = 0; i < 8; i++) CPA(sb + 16384u + asw0 + i * 2048u, bgp0 + bo + i * bstep);
        CP_COMMIT();
        if (1 < nIt) {
            offs(1, ao, bo);
            #pragma unroll
            for (int i = 0; i < 8; i++) CPA(sb + 32768u + asw0 + i * 2048u, agp0 + ao + i * astep);
            #pragma unroll
            for (int i = 0; i < 8; i++) CPA(sb + 49152u + asw0 + i * 2048u, bgp0 + bo + i * bstep);
        }
        CP_COMMIT();
    }

    int cur = 0;
    #pragma unroll 1
    for (int it = 0; it < nIt; ++it) {
        CP_WAIT1();
        __syncthreads();

        const uint32_t st = sb + (uint32_t)cur * 32768u;

        // preload ks=0 fragments (B all 8 nj, A for mi=0)
        uint32_t bf[2][8][2];
        uint32_t af[2][4];
        LDSM4(bf[0][0][0], bf[0][0][1], bf[0][1][0], bf[0][1][1], st + bbase[0]);
        LDSM4(bf[0][2][0], bf[0][2][1], bf[0][3][0], bf[0][3][1], st + bbase[1]);
        LDSM4(bf[0][4][0], bf[0][4][1], bf[0][5][0], bf[0][5][1], st + bbase[2]);
        LDSM4(bf[0][6][0], bf[0][6][1], bf[0][7][0], bf[0][7][1], st + bbase[3]);
        LDSM4(af[0][0], af[0][1], af[0][2], af[0][3], st + abase[0]);

        // issue next-next stage loads (latency overlapped with LDSM above)
        if (it + 2 < nIt) {
            long ao, bo;
            offs(it + 2, ao, bo);
            int nst = cur + 2; if (nst >= 3) nst -= 3;
            uint32_t stg = (uint32_t)nst * 32768u;
            #pragma unroll
            for (int i = 0; i < 8; i++) CPA(sb + stg + asw0 + i * 2048u, agp0 + ao + i * astep);
            #pragma unroll
            for (int i = 0; i < 8; i++) CPA(sb + stg + 16384u + asw0 + i * 2048u, bgp0 + bo + i * bstep);
        }
        CP_COMMIT();

        #pragma unroll
        for (int ks = 0; ks < 4; ks++) {
            const int cb = ks & 1;
            #pragma unroll
            for (int mi = 0; mi < 4; mi++) {
                // prefetch next fragments while MMAs below execute
                if (mi < 3) {
                    const uint32_t kx = (uint32_t)(ks << 5);
                    LDSM4(af[(mi + 1) & 1][0], af[(mi + 1) & 1][1],
                          af[(mi + 1) & 1][2], af[(mi + 1) & 1][3],
                          st + (abase[mi + 1] ^ kx));
                } else if (ks < 3) {
                    const int nb = cb ^ 1;
                    const uint32_t kxn = (uint32_t)((ks + 1) << 5);
                    LDSM4(bf[nb][0][0], bf[nb][0][1], bf[nb][1][0], bf[nb][1][1], st + (bbase[0] ^ kxn));
                    LDSM4(bf[nb][2][0], bf[nb][2][1], bf[nb][3][0], bf[nb][3][1], st + (bbase[1] ^ kxn));
                    LDSM4(bf[nb][4][0], bf[nb][4][1], bf[nb][5][0], bf[nb][5][1], st + (bbase[2] ^ kxn));
                    LDSM4(bf[nb][6][0], bf[nb][6][1], bf[nb][7][0], bf[nb][7][1], st + (bbase[3] ^ kxn));
                    LDSM4(af[0][0], af[0][1], af[0][2], af[0][3], st + (abase[0] ^ kxn));
                }
                const int ca = mi & 1;
                #pragma unroll
                for (int nj = 0; nj < 8; nj++)
                    MMA16816(acc[mi][nj], af[ca][0], af[ca][1], af[ca][2], af[ca][3],
                             bf[cb][nj][0], bf[cb][nj][1]);
            }
        }
        if (++cur == 3) cur = 0;
    }

    // ---------------- epilogue ----------------
    float* Cf = (float*)Cv + (long)blockIdx.z * sC;
    __nv_bfloat16* Cb = (__nv_bfloat16*)Cv + (long)blockIdx.z * sC;

    #pragma unroll
    for (int mi = 0; mi < 4; mi++) {
        const int m0 = bm + wm * 64 + mi * 16 + (lane >> 2);
        const int m1 = m0 + 8;
        const float bm0 = BIASM ? __ldg(&bias[m0]) : 0.f;
        const float bm1 = BIASM ? __ldg(&bias[m1]) : 0.f;
        float sc0 = 1.f, sc1 = 1.f;
        if (SCALEM) {
            sc0 = __ldg(&scalev[(long)blockIdx.z * LQ + m0]);
            sc1 = __ldg(&scalev[(long)blockIdx.z * LQ + m1]);
        }
        float s0 = 0.f, s1 = 0.f, q0 = 0.f, q1 = 0.f;
        #pragma unroll
        for (int nj = 0; nj < 8; nj++) {
            const int n = bn + wn * 64 + nj * 8 + (lane & 3) * 2;
            const float bn0 = BIASN ? __ldg(&bias[n])     : 0.f;
            const float bn1 = BIASN ? __ldg(&bias[n + 1]) : 0.f;
            float v00 = acc[mi][nj][0] + bm0 + bn0;
            float v01 = acc[mi][nj][1] + bm0 + bn1;
            float v10 = acc[mi][nj][2] + bm1 + bn0;
            float v11 = acc[mi][nj][3] + bm1 + bn1;
            if (SOFTEXP) {
                v00 = __expf(v00); v01 = __expf(v01);
                v10 = __expf(v10); v11 = __expf(v11);
                s0 += v00 + v01;
                s1 += v10 + v11;
            }
            if (BNSTAT) {
                s0 += v00 + v01; s1 += v10 + v11;
                q0 += v00 * v00 + v01 * v01;
                q1 += v10 * v10 + v11 * v11;
            }
            if (SCALEM) { v00 *= sc0; v01 *= sc0; v10 *= sc1; v11 *= sc1; }
            if (POOLM) {
                float p00 = fmaxf(v00, __shfl_xor_sync(~0u, v00, 4));
                float p01 = fmaxf(v01, __shfl_xor_sync(~0u, v01, 4));
                float p10 = fmaxf(v10, __shfl_xor_sync(~0u, v10, 4));
                float p11 = fmaxf(v11, __shfl_xor_sync(~0u, v11, 4));
                if (!(lane & 4)) {
                    int pr0 = m0 >> 1, pr1 = m1 >> 1;
                    __nv_bfloat16 h0 = __float2bfloat16(p00), h1 = __float2bfloat16(p01);
                    __nv_bfloat16 h2 = __float2bfloat16(p10), h3 = __float2bfloat16(p11);
                    __nv_bfloat162 hh0; hh0.x = h0; hh0.y = h1;
                    __nv_bfloat162 hh1; hh1.x = h2; hh1.y = h3;
                    __nv_bfloat162 ll0;
                    ll0.x = __float2bfloat16(p00 - __bfloat162float(h0));
                    ll0.y = __float2bfloat16(p01 - __bfloat162float(h1));
                    __nv_bfloat162 ll1;
                    ll1.x = __float2bfloat16(p10 - __bfloat162float(h2));
                    ll1.y = __float2bfloat16(p11 - __bfloat162float(h3));
                    *(__nv_bfloat162*)&Cb[(long)pr0 * ldc + n] = hh0;
                    *(__nv_bfloat162*)&Cb[(long)pr0 * ldc + lo_off + n] = ll0;
                    *(__nv_bfloat162*)&Cb[(long)pr1 * ldc + n] = hh1;
                    *(__nv_bfloat162*)&Cb[(long)pr1 * ldc + lo_off + n] = ll1;
                }
            } else if (POOLN) {
                float p0 = fmaxf(v00, v01);
                float p1 = fmaxf(v10, v11);
                int np = n >> 1;
                __nv_bfloat16 h0 = __float2bfloat16(p0);
                __nv_bfloat16 h1 = __float2bfloat16(p1);
                Cb[(long)m0 * ldc + np] = h0;
                Cb[(long)m0 * ldc + lo_off + np] = __float2bfloat16(p0 - __bfloat162float(h0));
                Cb[(long)m1 * ldc + np] = h1;
                Cb[(long)m1 * ldc + lo_off + np] = __float2bfloat16(p1 - __bfloat162float(h1));
            } else if (SPLIT || SOFTEXP) {
                __nv_bfloat16 h00 = __float2bfloat16(v00), h01 = __float2bfloat16(v01);
                __nv_bfloat16 h10 = __float2bfloat16(v10), h11 = __float2bfloat16(v11);
                __nv_bfloat162 hh0; hh0.x = h00; hh0.y = h01;
                __nv_bfloat162 hh1; hh1.x = h10; hh1.y = h11;
                __nv_bfloat162 ll0;
                ll0.x = __float2bfloat16(v00 - __bfloat162float(h00));
                ll0.y = __float2bfloat16(v01 - __bfloat162float(h01));
                __nv_bfloat162 ll1;
                ll1.x = __float2bfloat16(v10 - __bfloat162float(h10));
                ll1.y = __float2bfloat16(v11 - __bfloat162float(h11));
                *(__nv_bfloat162*)&Cb[(long)m0 * ldc + n] = hh0;
                *(__nv_bfloat162*)&Cb[(long)m0 * ldc + lo_off + n] = ll0;
                *(__nv_bfloat162*)&Cb[(long)m1 * ldc + n] = hh1;
                *(__nv_bfloat162*)&Cb[(long)m1 * ldc + lo_off + n] = ll1;
            } else {
                *(float2*)&Cf[(long)m0 * ldc + n] = make_float2(v00, v01);
                *(float2*)&Cf[(long)m1 * ldc + n] = make_float2(v10, v11);
            }
        }
        if (SOFTEXP) {
            s0 += __shfl_xor_sync(~0u, s0, 1);
            s0 += __shfl_xor_sync(~0u, s0, 2);
            s1 += __shfl_xor_sync(~0u, s1, 1);
            s1 += __shfl_xor_sync(~0u, s1, 2);
            if ((lane & 3) == 0) {
                long base = ((long)blockIdx.z * LQ + m0) * 32 + blockIdx.x * 2 + wn;
                psum[base] = s0;
                psum[base + 8 * 32] = s1;
            }
        }
        if (BNSTAT) {
            s0 += __shfl_xor_sync(~0u, s0, 1);
            s0 += __shfl_xor_sync(~0u, s0, 2);
            s1 += __shfl_xor_sync(~0u, s1, 1);
            s1 += __shfl_xor_sync(~0u, s1, 2);
            q0 += __shfl_xor_sync(~0u, q0, 1);
            q0 += __shfl_xor_sync(~0u, q0, 2);
            q1 += __shfl_xor_sync(~0u, q1, 1);
            q1 += __shfl_xor_sync(~0u, q1, 2);
            if ((lane & 3) == 0) {
                int col = blockIdx.z * 64 + blockIdx.x * 2 + wn;
                psum [(long)m0 * 512 + col] = s0;
                psum [(long)m1 * 512 + col] = s1;
                psumq[(long)m0 * 512 + col] = q0;
                psumq[(long)m1 * 512 + col] = q1;
            }
        }
    }
}

// --------------------------------------------------------------- aux kernels
__device__ __forceinline__ void split_store(__nv_bfloat16* hi_p, __nv_bfloat16* lo_p, float v) {
    __nv_bfloat16 h = __float2bfloat16(v);
    *hi_p = h;
    *lo_p = __float2bfloat16(v - __bfloat162float(h));
}

__global__ __launch_bounds__(256)
void wsplit_all_kernel(const float* __restrict__ tw, const float* __restrict__ pw,
                       const float* __restrict__ gw, const float* __restrict__ zw,
                       __nv_bfloat16* __restrict__ ot, __nv_bfloat16* __restrict__ op,
                       __nv_bfloat16* __restrict__ og, __nv_bfloat16* __restrict__ oz)
{
    int i = blockIdx.x * 256 + threadIdx.x;
    int which = i >> 17;
    int j = i & 131071;
    const float* w; __nv_bfloat16* o; int Kc;
    if      (which == 0) { w = tw; o = ot; Kc = 512; }
    else if (which == 1) { w = pw; o = op; Kc = 512; }
    else if (which == 2) { w = gw; o = og; Kc = 512; }
    else                 { w = zw; o = oz; Kc = 256; }
    int r = j / Kc, k = j - r * Kc;
    split_store(&o[(long)r * 2 * Kc + k], &o[(long)r * 2 * Kc + Kc + k], w[j]);
}

__global__ __launch_bounds__(256)
void transpose_split_kernel(const float* __restrict__ x, __nv_bfloat16* __restrict__ xt)
{
    __shared__ float t[32][33];
    int b = blockIdx.z;
    int l0 = blockIdx.x * 32, c0 = blockIdx.y * 32;
    int tx = threadIdx.x & 31, ty = threadIdx.x >> 5;
    const float* px = x + ((long)b * CFULL + c0) * LQ + l0;
    #pragma unroll
    for (int i = 0; i < 32; i += 8) t[ty + i][tx] = px[(long)(ty + i) * LQ + tx];
    __syncthreads();
    __nv_bfloat16* po = xt + ((long)b * LQ + l0) * 1024 + c0;
    #pragma unroll
    for (int i = 0; i < 32; i += 8) {
        float v = t[tx][ty + i];
        split_store(&po[(long)(ty + i) * 1024 + tx],
                    &po[(long)(ty + i) * 1024 + 512 + tx], v);
    }
}

__global__ __launch_bounds__(256)
void rowsum_inv_kernel(const float* __restrict__ psum, float* __restrict__ inv)
{
    int row = blockIdx.x * 8 + (threadIdx.x >> 5);
    int lane = threadIdx.x & 31;
    float s = psum[(long)row * 32 + lane];
    #pragma unroll
    for (int o = 16; o; o >>= 1) s += __shfl_xor_sync(~0u, s, o);
    if (lane == 0) inv[row] = 1.f / s;
}

__global__ __launch_bounds__(256)
void bn_reduce_kernel(const float* __restrict__ bns, const float* __restrict__ bnq,
                      float* __restrict__ mean, float* __restrict__ var)
{
    __shared__ float ss_s[8], ss_q[8];
    int c = blockIdx.x, tid = threadIdx.x, lane = tid & 31, warp = tid >> 5;
    float s = 0.f, q = 0.f;
    #pragma unroll
    for (int i = 0; i < 2; i++) {
        s += bns[(long)c * 512 + tid + i * 256];
        q += bnq[(long)c * 512 + tid + i * 256];
    }
    #pragma unroll
    for (int o = 16; o; o >>= 1) {
        s += __shfl_xor_sync(~0u, s, o);
        q += __shfl_xor_sync(~0u, q, o);
    }
    if (lane == 0) { ss_s[warp] = s; ss_q[warp] = q; }
    __syncthreads();
    if (tid == 0) {
        float S = 0.f, Q = 0.f;
        #pragma unroll
        for (int w = 0; w < 8; w++) { S += ss_s[w]; Q += ss_q[w]; }
        const float invN = 1.f / (float)(BATCH * LQ);
        float mu = S * invN;
        mean[c] = mu;
        var[c] = Q * invN - mu * mu;
    }
}

__global__ __launch_bounds__(256)
void bn_apply_kernel(const float* __restrict__ z, const float* __restrict__ x,
                     const float* __restrict__ gamma, const float* __restrict__ beta,
                     const float* __restrict__ mean, const float* __restrict__ var,
                     float* __restrict__ out)
{
    long base = ((long)blockIdx.x * 256 + threadIdx.x) * 4;
    int c = (int)((base >> 12) & (CFULL - 1));
    float scale = gamma[c] * rsqrtf(var[c] + 1e-5f);
    float shift = beta[c] - mean[c] * scale;
    float4 zv = *(const float4*)&z[base];
    float4 xv = *(const float4*)&x[base];
    float4 o;
    o.x = zv.x * scale + shift + xv.x;
    o.y = zv.y * scale + shift + xv.y;
    o.z = zv.z * scale + shift + xv.z;
    o.w = zv.w * scale + shift + xv.w;
    *(float4*)&out[base] = o;
}

// --------------------------------------------------------------- launch
extern "C" void kernel_launch(void* const* d_in, const int* in_sizes, int n_in,
                              void* d_out, int out_size)
{
    const float* x       = (const float*)d_in[0];
    const float* theta_w = (const float*)d_in[1];
    const float* theta_b = (const float*)d_in[2];
    const float* phi_w   = (const float*)d_in[3];
    const float* phi_b   = (const float*)d_in[4];
    const float* g_w     = (const float*)d_in[5];
    const float* g_b     = (const float*)d_in[6];
    const float* wz_w    = (const float*)d_in[7];
    const float* wz_b    = (const float*)d_in[8];
    const float* gamma   = (const float*)d_in[9];
    const float* beta    = (const float*)d_in[10];
    float* out = (float*)d_out;

    __nv_bfloat16 *xt, *thetaT, *phiPT, *gP, *fs, *yT, *wth, *wph, *wg, *wwz;
    float *psum, *inv, *z, *bns, *bnq, *mean, *var;
    cudaGetSymbolAddress((void**)&xt,     g_xt);
    cudaGetSymbolAddress((void**)&thetaT, g_thetaT);
    cudaGetSymbolAddress((void**)&phiPT,  g_phiPT);
    cudaGetSymbolAddress((void**)&gP,     g_gP);
    cudaGetSymbolAddress((void**)&fs,     g_fs);
    cudaGetSymbolAddress((void**)&psum,   g_psum);
    cudaGetSymbolAddress((void**)&inv,    g_inv);
    cudaGetSymbolAddress((void**)&yT,     g_yT);
    cudaGetSymbolAddress((void**)&z,      g_z);
    cudaGetSymbolAddress((void**)&bns,    g_bns);
    cudaGetSymbolAddress((void**)&bnq,    g_bnq);
    cudaGetSymbolAddress((void**)&wth,    g_wth);
    cudaGetSymbolAddress((void**)&wph,    g_wph);
    cudaGetSymbolAddress((void**)&wg,     g_wg);
    cudaGetSymbolAddress((void**)&wwz,    g_wwz);
    cudaGetSymbolAddress((void**)&mean,   g_mean);
    cudaGetSymbolAddress((void**)&var,    g_var);

    cudaFuncSetAttribute((const void*)mma_gemm<0,1,1,0,0,0,0,0>, cudaFuncAttributeMaxDynamicSharedMemorySize, SM_BYTES);
    cudaFuncSetAttribute((const void*)mma_gemm<0,1,1,1,0,0,0,0>, cudaFuncAttributeMaxDynamicSharedMemorySize, SM_BYTES);
    cudaFuncSetAttribute((const void*)mma_gemm<1,0,1,0,1,0,0,0>, cudaFuncAttributeMaxDynamicSharedMemorySize, SM_BYTES);
    cudaFuncSetAttribute((const void*)mma_gemm<0,0,0,0,0,1,0,0>, cudaFuncAttributeMaxDynamicSharedMemorySize, SM_BYTES);
    cudaFuncSetAttribute((const void*)mma_gemm<0,0,1,0,0,0,1,0>, cudaFuncAttributeMaxDynamicSharedMemorySize, SM_BYTES);
    cudaFuncSetAttribute((const void*)mma_gemm<1,0,0,0,0,0,0,1>, cudaFuncAttributeMaxDynamicSharedMemorySize, SM_BYTES);

    dim3 blk(256);
    dim3 mblk(128);

    // side streams + fork/join events for independent GEMMs (capture-legal)
    cudaStream_t sB, sC;
    cudaStreamCreateWithFlags(&sB, cudaStreamNonBlocking);
    cudaStreamCreateWithFlags(&sC, cudaStreamNonBlocking);
    cudaEvent_t eRoot, eG, ePhi;
    cudaEventCreateWithFlags(&eRoot, cudaEventDisableTiming);
    cudaEventCreateWithFlags(&eG,    cudaEventDisableTiming);
    cudaEventCreateWithFlags(&ePhi,  cudaEventDisableTiming);

    wsplit_all_kernel<<<2048, blk>>>(theta_w, phi_w, g_w, wz_w, wth, wph, wg, wwz);
    transpose_split_kernel<<<dim3(LQ / 32, CFULL / 32, BATCH), blk>>>(x, xt);

    // fork point: xt + weights ready
    cudaEventRecord(eRoot, 0);
    cudaStreamWaitEvent(sB, eRoot, 0);
    cudaStreamWaitEvent(sC, eRoot, 0);

    // gP[Ci,L/2] split = maxpool_n(g_w * xT^T + bias m)   [stream B — only y-GEMM needs it]
    mma_gemm<1,0,1,0,1,0,0,0><<<dim3(32, 2, BATCH), mblk, SM_BYTES, sB>>>(
        wg, xt, g_b, nullptr, nullptr, nullptr, gP, 512, 1024, 1024, 4096, 2048,
        0L, (long)LQ * 1024, (long)CI * 4096);
    cudaEventRecord(eG, sB);

    // phiP[L/2,Ci] split = maxpool_m(xT * phi_w^T + bias n)   [stream C]
    mma_gemm<0,1,1,1,0,0,0,0><<<dim3(2, 32, BATCH), mblk, SM_BYTES, sC>>>(
        xt, wph, phi_b, nullptr, nullptr, nullptr, phiPT, 512, 1024, 1024, 512, 256,
        (long)LQ * 1024, 0L, (long)LK * 512);
    cudaEventRecord(ePhi, sC);

    // thetaT[L,Ci] split = xT * theta_w^T  (+bias n)   [main stream]
    mma_gemm<0,1,1,0,0,0,0,0><<<dim3(2, 32, BATCH), mblk, SM_BYTES>>>(
        xt, wth, theta_b, nullptr, nullptr, nullptr, thetaT, 512, 1024, 1024, 512, 256,
        (long)LQ * 1024, 0L, (long)LQ * 512);

    // join phi before f-GEMM
    cudaStreamWaitEvent(0, ePhi, 0);

    // fs = exp(thetaT * phiP^T) split bf16, plus partial row sums
    mma_gemm<0,0,0,0,0,1,0,0><<<dim3(16, 32, BATCH), mblk, SM_BYTES>>>(
        thetaT, phiPT, nullptr, nullptr, psum, nullptr, fs, 256, 512, 512, 4096, 2048,
        (long)LQ * 512, (long)LK * 512, (long)LQ * 4096);

    rowsum_inv_kernel<<<BATCH * LQ / 8, blk>>>(psum, inv);

    // join g before y-GEMM (g ran concurrent with f-GEMM)
    cudaStreamWaitEvent(0, eG, 0);

    // yT[L,Ci] split = (fs_split * gP_split^T) * inv[row]  (3 terms)
    mma_gemm<0,0,1,0,0,0,1,0><<<dim3(2, 32, BATCH), mblk, SM_BYTES>>>(
        fs, gP, nullptr, inv, nullptr, nullptr, yT, 2048, 4096, 4096, 512, 256,
        (long)LQ * 4096, (long)CI * 4096, (long)LQ * 512);

    // z[C,L] fp32 = wz_w * yT^T  (+bias m), with fused BN partial stats
    mma_gemm<1,0,0,0,0,0,0,1><<<dim3(32, 4, BATCH), mblk, SM_BYTES>>>(
        wwz, yT, wz_b, nullptr, bns, bnq, z, 256, 512, 512, LQ, 0,
        0L, (long)LQ * 512, (long)CFULL * LQ);

    bn_reduce_kernel<<<CFULL, blk>>>(bns, bnq, mean, var);
    bn_apply_kernel<<<(BATCH * CFULL * LQ) / (256 * 4), blk>>>(
        z, x, gamma, beta, mean, var, out);

    cudaStreamDestroy(sB);
    cudaStreamDestroy(sC);
    cudaEventDestroy(eRoot);
    cudaEventDestroy(eG);
    cudaEventDestroy(ePhi);
}

// round 11
// speedup vs baseline: 1.5263x; 1.5263x over previous
#include <cuda_runtime.h>
#include <cuda_bf16.h>
#include <cstdint>

#define BATCH 8
#define CFULL 512
#define CI    256
#define LQ    4096
#define LK    2048

#define SWZ(x) ((x) ^ (((x) >> 3) & 0x70))

__device__ __forceinline__ uint32_t smem_u32(const void* p) {
    uint32_t a;
    asm("{ .reg .u64 t; cvta.to.shared.u64 t, %1; cvt.u32.u64 %0, t; }" : "=r"(a) : "l"(p));
    return a;
}

#define CPA(saddr, gptr) \
    asm volatile("cp.async.cg.shared.global [%0], [%1], 16;" :: "r"(saddr), "l"(gptr))
#define CP_COMMIT() asm volatile("cp.async.commit_group;" ::: "memory")
#define CP_WAIT1()  asm volatile("cp.async.wait_group 1;" ::: "memory")

#define LDSM4(r0, r1, r2, r3, addr) \
    asm volatile("ldmatrix.sync.aligned.m8n8.x4.shared.b16 {%0,%1,%2,%3}, [%4];" \
        : "=r"(r0), "=r"(r1), "=r"(r2), "=r"(r3) : "r"(addr))

#define MMA16816(d, a0, a1, a2, a3, b0, b1) \
    asm volatile("mma.sync.aligned.m16n8k16.row.col.f32.bf16.bf16.f32 " \
        "{%0,%1,%2,%3}, {%4,%5,%6,%7}, {%8,%9}, {%0,%1,%2,%3};" \
        : "+f"((d)[0]), "+f"((d)[1]), "+f"((d)[2]), "+f"((d)[3]) \
        : "r"(a0), "r"(a1), "r"(a2), "r"(a3), "r"(b0), "r"(b1))

// --------------------------------------------------------------- scratch
__device__ __nv_bfloat16 g_xt    [(size_t)BATCH * LQ * 1024];     // xT split [B][L][2C]
__device__ __nv_bfloat16 g_thetaT[(size_t)BATCH * LQ * 512];      // [B][L][2Ci]
__device__ __nv_bfloat16 g_phiPT [(size_t)BATCH * LK * 512];      // [B][L/2][2Ci]
__device__ __nv_bfloat16 g_gP    [(size_t)BATCH * CI * 4096];     // [B][Ci][2*L/2] split
__device__ __nv_bfloat16 g_fs    [(size_t)BATCH * LQ * 4096];     // exp(f) split
__device__ float         g_psum  [(size_t)BATCH * LQ * 32];       // partial row sums
__device__ float         g_inv   [(size_t)BATCH * LQ];            // 1/rowsum
__device__ __nv_bfloat16 g_yT    [(size_t)BATCH * LQ * 512];      // [B][L][2Ci]
__device__ float         g_z     [(size_t)BATCH * CFULL * LQ];    // [B][C][L]
__device__ float         g_bns   [(size_t)CFULL * 512];           // BN partial sums
__device__ float         g_bnq   [(size_t)CFULL * 512];           // BN partial sumsq
__device__ __nv_bfloat16 g_wth   [CI * 1024];
__device__ __nv_bfloat16 g_wph   [CI * 1024];
__device__ __nv_bfloat16 g_wg    [CI * 1024];
__device__ __nv_bfloat16 g_wwz   [CFULL * 512];
__device__ float g_mean[CFULL];
__device__ float g_var [CFULL];

// ---------------- shared mainloop (BK=64, 3-stage, frag double-buffer) ------
// Computes acc[4][8][4] for a 128x128 tile, 4 warps (2m x 2n), warp 64x64.
// A[128 rows @ lda], B[128 rows @ ldb], K columns, 3 split terms.
struct MainloopOut { float acc[4][8][4]; };

__device__ __forceinline__ void run_mainloop(
    const __nv_bfloat16* __restrict__ A, const __nv_bfloat16* __restrict__ B,
    int K, int lda, int ldb,
    uint32_t sb, int tid, const uint32_t* abase, const uint32_t* bbase,
    float acc[4][8][4])
{
    const int r0 = tid >> 3;
    const int c0 = tid & 7;
    const __nv_bfloat16* agp0 = A + (long)r0 * lda + c0 * 8;
    const __nv_bfloat16* bgp0 = B + (long)r0 * ldb + c0 * 8;
    const uint32_t asw0 = SWZ((uint32_t)(r0 * 128 + c0 * 16));
    const long astep = 16L * lda;
    const long bstep = 16L * ldb;

    const int kper = K >> 6;
    const int nIt = 3 * kper;

    auto offs = [&](int n, long& ao, long& bo) {
        int term = n / kper;
        int kk = (n - term * kper) << 6;
        ao = ((term == 2) ? (long)K : 0L) + kk;
        bo = ((term == 1) ? (long)K : 0L) + kk;
    };

    {   // prologue: stages 0 and 1
        long ao, bo;
        offs(0, ao, bo);
        #pragma unroll
        for (int i = 0; i < 8; i++) CPA(sb + asw0 + i * 2048u, agp0 + ao + i * astep);
        #pragma unroll
        for (int i = 0; i < 8; i++) CPA(sb + 16384u + asw0 + i * 2048u, bgp0 + bo + i * bstep);
        CP_COMMIT();
        offs(1, ao, bo);
        #pragma unroll
        for (int i = 0; i < 8; i++) CPA(sb + 32768u + asw0 + i * 2048u, agp0 + ao + i * astep);
        #pragma unroll
        for (int i = 0; i < 8; i++) CPA(sb + 49152u + asw0 + i * 2048u, bgp0 + bo + i * bstep);
        CP_COMMIT();
    }

    int cur = 0;
    #pragma unroll 1
    for (int it = 0; it < nIt; ++it) {
        CP_WAIT1();
        __syncthreads();

        const uint32_t st = sb + (uint32_t)cur * 32768u;

        uint32_t bf[2][8][2];
        uint32_t af[2][4];
        LDSM4(bf[0][0][0], bf[0][0][1], bf[0][1][0], bf[0][1][1], st + bbase[0]);
        LDSM4(bf[0][2][0], bf[0][2][1], bf[0][3][0], bf[0][3][1], st + bbase[1]);
        LDSM4(bf[0][4][0], bf[0][4][1], bf[0][5][0], bf[0][5][1], st + bbase[2]);
        LDSM4(bf[0][6][0], bf[0][6][1], bf[0][7][0], bf[0][7][1], st + bbase[3]);
        LDSM4(af[0][0], af[0][1], af[0][2], af[0][3], st + abase[0]);

        if (it + 2 < nIt) {
            long ao, bo;
            offs(it + 2, ao, bo);
            int nst = cur + 2; if (nst >= 3) nst -= 3;
            uint32_t stg = (uint32_t)nst * 32768u;
            #pragma unroll
            for (int i = 0; i < 8; i++) CPA(sb + stg + asw0 + i * 2048u, agp0 + ao + i * astep);
            #pragma unroll
            for (int i = 0; i < 8; i++) CPA(sb + stg + 16384u + asw0 + i * 2048u, bgp0 + bo + i * bstep);
        }
        CP_COMMIT();

        #pragma unroll
        for (int ks = 0; ks < 4; ks++) {
            const int cb = ks & 1;
            #pragma unroll
            for (int mi = 0; mi < 4; mi++) {
                if (mi < 3) {
                    const uint32_t kx = (uint32_t)(ks << 5);
                    LDSM4(af[(mi + 1) & 1][0], af[(mi + 1) & 1][1],
                          af[(mi + 1) & 1][2], af[(mi + 1) & 1][3],
                          st + (abase[mi + 1] ^ kx));
                } else if (ks < 3) {
                    const int nb = cb ^ 1;
                    const uint32_t kxn = (uint32_t)((ks + 1) << 5);
                    LDSM4(bf[nb][0][0], bf[nb][0][1], bf[nb][1][0], bf[nb][1][1], st + (bbase[0] ^ kxn));
                    LDSM4(bf[nb][2][0], bf[nb][2][1], bf[nb][3][0], bf[nb][3][1], st + (bbase[1] ^ kxn));
                    LDSM4(bf[nb][4][0], bf[nb][4][1], bf[nb][5][0], bf[nb][5][1], st + (bbase[2] ^ kxn));
                    LDSM4(bf[nb][6][0], bf[nb][6][1], bf[nb][7][0], bf[nb][7][1], st + (bbase[3] ^ kxn));
                    LDSM4(af[0][0], af[0][1], af[0][2], af[0][3], st + (abase[0] ^ kxn));
                }
                const int ca = mi & 1;
                #pragma unroll
                for (int nj = 0; nj < 8; nj++)
                    MMA16816(acc[mi][nj], af[ca][0], af[ca][1], af[ca][2], af[ca][3],
                             bf[cb][nj][0], bf[cb][nj][1]);
            }
        }
        if (++cur == 3) cur = 0;
    }
}

__device__ __forceinline__ void frag_bases(int wid, int lane, uint32_t* abase, uint32_t* bbase)
{
    const int wm = wid >> 1;
    const int wn = wid & 1;
    #pragma unroll
    for (int mi = 0; mi < 4; mi++) {
        int arow = wm * 64 + mi * 16 + (lane & 15);
        abase[mi] = (uint32_t)(arow * 128) + ((((lane >> 4) << 4)) ^ ((arow & 7) << 4));
    }
    #pragma unroll
    for (int j2 = 0; j2 < 4; j2++) {
        int brow = wn * 64 + j2 * 16 + (lane & 7) + ((lane >> 4) << 3);
        uint32_t bcol = ((lane >> 3) & 1) << 4;
        bbase[j2] = 16384u + (uint32_t)(brow * 128) + (bcol ^ ((brow & 7) << 4));
    }
}

__device__ __forceinline__ void bsplit2(__nv_bfloat16* base, long row, int ldc, int lo_off,
                                        int n, float v0, float v1)
{
    __nv_bfloat16 h0 = __float2bfloat16(v0), h1 = __float2bfloat16(v1);
    __nv_bfloat162 hh; hh.x = h0; hh.y = h1;
    __nv_bfloat162 ll;
    ll.x = __float2bfloat16(v0 - __bfloat162float(h0));
    ll.y = __float2bfloat16(v1 - __bfloat162float(h1));
    *(__nv_bfloat162*)&base[row * ldc + n] = hh;
    *(__nv_bfloat162*)&base[row * ldc + lo_off + n] = ll;
}

// ---------------- merged projection GEMM (theta | phi | g) ------------------
// grid (192, BATCH): id<64 theta, <128 phi, else g. All K=512, lda=ldb=1024.
#define SM_BYTES 98304
__global__ __launch_bounds__(128, 2)
void proj_gemm(const float* __restrict__ theta_b, const float* __restrict__ phi_b,
               const float* __restrict__ g_b)
{
    extern __shared__ char smem[];
    const uint32_t sb = smem_u32(smem);
    const int tid = threadIdx.x;
    const int wid = tid >> 5;
    const int lane = tid & 31;
    const int b = blockIdx.y;
    const int id = blockIdx.x;
    const int kind = id >> 6;          // 0 theta, 1 phi, 2 g
    const int sub = id & 63;

    int bm, bn;
    const __nv_bfloat16 *A, *B;
    const __nv_bfloat16* xtb = g_xt + (size_t)b * LQ * 1024;
    if (kind < 2) {
        bm = (sub >> 1) * 128;         // over LQ
        bn = (sub & 1) * 128;          // over Ci
        A = xtb + (long)bm * 1024;
        B = (kind == 0 ? g_wth : g_wph) + (long)bn * 1024;
    } else {
        bm = (sub >> 5) * 128;         // over Ci
        bn = (sub & 31) * 128;         // over LQ
        A = g_wg + (long)bm * 1024;
        B = xtb + (long)bn * 1024;
    }

    uint32_t abase[4], bbase[4];
    frag_bases(wid, lane, abase, bbase);

    float acc[4][8][4];
    #pragma unroll
    for (int i = 0; i < 4; i++)
        #pragma unroll
        for (int j = 0; j < 8; j++)
            #pragma unroll
            for (int q = 0; q < 4; q++)
                acc[i][j][q] = 0.f;

    run_mainloop(A, B, 512, 1024, 1024, sb, tid, abase, bbase, acc);

    // ---------------- epilogue ----------------
    const int wm = wid >> 1;
    const int wn = wid & 1;

    #pragma unroll
    for (int mi = 0; mi < 4; mi++) {
        const int m0 = bm + wm * 64 + mi * 16 + (lane >> 2);
        const int m1 = m0 + 8;
        float bm0 = 0.f, bm1 = 0.f;
        if (kind == 2) { bm0 = __ldg(&g_b[m0]); bm1 = __ldg(&g_b[m1]); }
        #pragma unroll
        for (int nj = 0; nj < 8; nj++) {
            const int n = bn + wn * 64 + nj * 8 + (lane & 3) * 2;
            float bn0 = 0.f, bn1 = 0.f;
            if (kind == 0) { bn0 = __ldg(&theta_b[n]); bn1 = __ldg(&theta_b[n + 1]); }
            else if (kind == 1) { bn0 = __ldg(&phi_b[n]); bn1 = __ldg(&phi_b[n + 1]); }
            float v00 = acc[mi][nj][0] + bm0 + bn0;
            float v01 = acc[mi][nj][1] + bm0 + bn1;
            float v10 = acc[mi][nj][2] + bm1 + bn0;
            float v11 = acc[mi][nj][3] + bm1 + bn1;
            if (kind == 0) {
                __nv_bfloat16* C = g_thetaT + (size_t)b * LQ * 512;
                bsplit2(C, m0, 512, 256, n, v00, v01);
                bsplit2(C, m1, 512, 256, n, v10, v11);
            } else if (kind == 1) {
                // pool over m pairs: rows (2r,2r+1) in lanes differing by bit 2
                float p00 = fmaxf(v00, __shfl_xor_sync(~0u, v00, 4));
                float p01 = fmaxf(v01, __shfl_xor_sync(~0u, v01, 4));
                float p10 = fmaxf(v10, __shfl_xor_sync(~0u, v10, 4));
                float p11 = fmaxf(v11, __shfl_xor_sync(~0u, v11, 4));
                if (!(lane & 4)) {
                    __nv_bfloat16* C = g_phiPT + (size_t)b * LK * 512;
                    bsplit2(C, m0 >> 1, 512, 256, n, p00, p01);
                    bsplit2(C, m1 >> 1, 512, 256, n, p10, p11);
                }
            } else {
                // pool over n pairs: adjacent columns in-thread
                float p0 = fmaxf(v00, v01);
                float p1 = fmaxf(v10, v11);
                int np = n >> 1;
                __nv_bfloat16* C = g_gP + (size_t)b * CI * 4096;
                __nv_bfloat16 h0 = __float2bfloat16(p0);
                __nv_bfloat16 h1 = __float2bfloat16(p1);
                C[(long)m0 * 4096 + np] = h0;
                C[(long)m0 * 4096 + 2048 + np] = __float2bfloat16(p0 - __bfloat162float(h0));
                C[(long)m1 * 4096 + np] = h1;
                C[(long)m1 * 4096 + 2048 + np] = __float2bfloat16(p1 - __bfloat162float(h1));
            }
        }
    }
}

// ---------------- templated GEMM for f / y / z -------------------------------
template<int BIASM, int SOFTEXP, int SCALEM, int BNSTAT>
__global__ __launch_bounds__(128, 2)
void mma_gemm(const __nv_bfloat16* __restrict__ A, const __nv_bfloat16* __restrict__ B,
              const float* __restrict__ bias, const float* __restrict__ scalev,
              float* __restrict__ psum, float* __restrict__ psumq,
              void* __restrict__ Cv,
              int K, int lda, int ldb, int ldc, int lo_off,
              long sA, long sB, long sC)
{
    extern __shared__ char smem[];
    const uint32_t sb = smem_u32(smem);
    const int tid = threadIdx.x;
    const int wid = tid >> 5;
    const int lane = tid & 31;
    const int bm = blockIdx.y * 128;
    const int bn = blockIdx.x * 128;
    A += (long)blockIdx.z * sA + (long)bm * lda;
    B += (long)blockIdx.z * sB + (long)bn * ldb;

    uint32_t abase[4], bbase[4];
    frag_bases(wid, lane, abase, bbase);

    float acc[4][8][4];
    #pragma unroll
    for (int i = 0; i < 4; i++)
        #pragma unroll
        for (int j = 0; j < 8; j++)
            #pragma unroll
            for (int q = 0; q < 4; q++)
                acc[i][j][q] = 0.f;

    run_mainloop(A, B, K, lda, ldb, sb, tid, abase, bbase, acc);

    const int wm = wid >> 1;
    const int wn = wid & 1;
    float* Cf = (float*)Cv + (long)blockIdx.z * sC;
    __nv_bfloat16* Cb = (__nv_bfloat16*)Cv + (long)blockIdx.z * sC;

    #pragma unroll
    for (int mi = 0; mi < 4; mi++) {
        const int m0 = bm + wm * 64 + mi * 16 + (lane >> 2);
        const int m1 = m0 + 8;
        const float bm0 = BIASM ? __ldg(&bias[m0]) : 0.f;
        const float bm1 = BIASM ? __ldg(&bias[m1]) : 0.f;
        float sc0 = 1.f, sc1 = 1.f;
        if (SCALEM) {
            sc0 = __ldg(&scalev[(long)blockIdx.z * LQ + m0]);
            sc1 = __ldg(&scalev[(long)blockIdx.z * LQ + m1]);
        }
        float s0 = 0.f, s1 = 0.f, q0 = 0.f, q1 = 0.f;
        #pragma unroll
        for (int nj = 0; nj < 8; nj++) {
            const int n = bn + wn * 64 + nj * 8 + (lane & 3) * 2;
            float v00 = acc[mi][nj][0] + bm0;
            float v01 = acc[mi][nj][1] + bm0;
            float v10 = acc[mi][nj][2] + bm1;
            float v11 = acc[mi][nj][3] + bm1;
            if (SOFTEXP) {
                v00 = __expf(v00); v01 = __expf(v01);
                v10 = __expf(v10); v11 = __expf(v11);
                s0 += v00 + v01;
                s1 += v10 + v11;
            }
            if (BNSTAT) {
                s0 += v00 + v01; s1 += v10 + v11;
                q0 += v00 * v00 + v01 * v01;
                q1 += v10 * v10 + v11 * v11;
            }
            if (SCALEM) { v00 *= sc0; v01 *= sc0; v10 *= sc1; v11 *= sc1; }
            if (SOFTEXP || SCALEM) {
                bsplit2(Cb, m0, ldc, lo_off, n, v00, v01);
                bsplit2(Cb, m1, ldc, lo_off, n, v10, v11);
            } else {
                *(float2*)&Cf[(long)m0 * ldc + n] = make_float2(v00, v01);
                *(float2*)&Cf[(long)m1 * ldc + n] = make_float2(v10, v11);
            }
        }
        if (SOFTEXP) {
            s0 += __shfl_xor_sync(~0u, s0, 1);
            s0 += __shfl_xor_sync(~0u, s0, 2);
            s1 += __shfl_xor_sync(~0u, s1, 1);
            s1 += __shfl_xor_sync(~0u, s1, 2);
            if ((lane & 3) == 0) {
                long base = ((long)blockIdx.z * LQ + m0) * 32 + blockIdx.x * 2 + wn;
                psum[base] = s0;
                psum[base + 8 * 32] = s1;
            }
        }
        if (BNSTAT) {
            s0 += __shfl_xor_sync(~0u, s0, 1);
            s0 += __shfl_xor_sync(~0u, s0, 2);
            s1 += __shfl_xor_sync(~0u, s1, 1);
            s1 += __shfl_xor_sync(~0u, s1, 2);
            q0 += __shfl_xor_sync(~0u, q0, 1);
            q0 += __shfl_xor_sync(~0u, q0, 2);
            q1 += __shfl_xor_sync(~0u, q1, 1);
            q1 += __shfl_xor_sync(~0u, q1, 2);
            if ((lane & 3) == 0) {
                int col = blockIdx.z * 64 + blockIdx.x * 2 + wn;
                psum [(long)m0 * 512 + col] = s0;
                psum [(long)m1 * 512 + col] = s1;
                psumq[(long)m0 * 512 + col] = q0;
                psumq[(long)m1 * 512 + col] = q1;
            }
        }
    }
}

// --------------------------------------------------------------- aux kernels
__device__ __forceinline__ void split_store(__nv_bfloat16* hi_p, __nv_bfloat16* lo_p, float v) {
    __nv_bfloat16 h = __float2bfloat16(v);
    *hi_p = h;
    *lo_p = __float2bfloat16(v - __bfloat162float(h));
}

__global__ __launch_bounds__(256)
void wsplit_all_kernel(const float* __restrict__ tw, const float* __restrict__ pw,
                       const float* __restrict__ gw, const float* __restrict__ zw)
{
    int i = blockIdx.x * 256 + threadIdx.x;
    int which = i >> 17;
    int j = i & 131071;
    const float* w; __nv_bfloat16* o; int Kc;
    if      (which == 0) { w = tw; o = g_wth; Kc = 512; }
    else if (which == 1) { w = pw; o = g_wph; Kc = 512; }
    else if (which == 2) { w = gw; o = g_wg;  Kc = 512; }
    else                 { w = zw; o = g_wwz; Kc = 256; }
    int r = j / Kc, k = j - r * Kc;
    split_store(&o[(long)r * 2 * Kc + k], &o[(long)r * 2 * Kc + Kc + k], w[j]);
}

__global__ __launch_bounds__(256)
void transpose_split_kernel(const float* __restrict__ x)
{
    __shared__ float t[32][33];
    int b = blockIdx.z;
    int l0 = blockIdx.x * 32, c0 = blockIdx.y * 32;
    int tx = threadIdx.x & 31, ty = threadIdx.x >> 5;
    const float* px = x + ((long)b * CFULL + c0) * LQ + l0;
    #pragma unroll
    for (int i = 0; i < 32; i += 8) t[ty + i][tx] = px[(long)(ty + i) * LQ + tx];
    __syncthreads();
    __nv_bfloat16* po = g_xt + ((size_t)b * LQ + l0) * 1024 + c0;
    #pragma unroll
    for (int i = 0; i < 32; i += 8) {
        float v = t[tx][ty + i];
        split_store(&po[(long)(ty + i) * 1024 + tx],
                    &po[(long)(ty + i) * 1024 + 512 + tx], v);
    }
}

__global__ __launch_bounds__(256)
void rowsum_inv_kernel()
{
    int row = blockIdx.x * 8 + (threadIdx.x >> 5);
    int lane = threadIdx.x & 31;
    float s = g_psum[(long)row * 32 + lane];
    #pragma unroll
    for (int o = 16; o; o >>= 1) s += __shfl_xor_sync(~0u, s, o);
    if (lane == 0) g_inv[row] = 1.f / s;
}

__global__ __launch_bounds__(256)
void bn_reduce_kernel()
{
    __shared__ float ss_s[8], ss_q[8];
    int c = blockIdx.x, tid = threadIdx.x, lane = tid & 31, warp = tid >> 5;
    float s = 0.f, q = 0.f;
    #pragma unroll
    for (int i = 0; i < 2; i++) {
        s += g_bns[(long)c * 512 + tid + i * 256];
        q += g_bnq[(long)c * 512 + tid + i * 256];
    }
    #pragma unroll
    for (int o = 16; o; o >>= 1) {
        s += __shfl_xor_sync(~0u, s, o);
        q += __shfl_xor_sync(~0u, q, o);
    }
    if (lane == 0) { ss_s[warp] = s; ss_q[warp] = q; }
    __syncthreads();
    if (tid == 0) {
        float S = 0.f, Q = 0.f;
        #pragma unroll
        for (int w = 0; w < 8; w++) { S += ss_s[w]; Q += ss_q[w]; }
        const float invN = 1.f / (float)(BATCH * LQ);
        float mu = S * invN;
        g_mean[c] = mu;
        g_var[c] = Q * invN - mu * mu;
    }
}

__global__ __launch_bounds__(256)
void bn_apply_kernel(const float* __restrict__ x,
                     const float* __restrict__ gamma, const float* __restrict__ beta,
                     float* __restrict__ out)
{
    long base = ((long)blockIdx.x * 256 + threadIdx.x) * 4;
    int c = (int)((base >> 12) & (CFULL - 1));
    float scale = gamma[c] * rsqrtf(g_var[c] + 1e-5f);
    float shift = beta[c] - g_mean[c] * scale;
    float4 zv = *(const float4*)&g_z[base];
    float4 xv = *(const float4*)&x[base];
    float4 o;
    o.x = zv.x * scale + shift + xv.x;
    o.y = zv.y * scale + shift + xv.y;
    o.z = zv.z * scale + shift + xv.z;
    o.w = zv.w * scale + shift + xv.w;
    *(float4*)&out[base] = o;
}

// --------------------------------------------------------------- launch
extern "C" void kernel_launch(void* const* d_in, const int* in_sizes, int n_in,
                              void* d_out, int out_size)
{
    const float* x       = (const float*)d_in[0];
    const float* theta_w = (const float*)d_in[1];
    const float* theta_b = (const float*)d_in[2];
    const float* phi_w   = (const float*)d_in[3];
    const float* phi_b   = (const float*)d_in[4];
    const float* g_w     = (const float*)d_in[5];
    const float* g_b     = (const float*)d_in[6];
    const float* wz_w    = (const float*)d_in[7];
    const float* wz_b    = (const float*)d_in[8];
    const float* gamma   = (const float*)d_in[9];
    const float* beta    = (const float*)d_in[10];
    float* out = (float*)d_out;

    __nv_bfloat16 *thetaT, *phiPT, *gP, *fs, *yT, *wwz;
    float *psum, *inv, *z, *bns, *bnq;
    cudaGetSymbolAddress((void**)&thetaT, g_thetaT);
    cudaGetSymbolAddress((void**)&phiPT,  g_phiPT);
    cudaGetSymbolAddress((void**)&gP,     g_gP);
    cudaGetSymbolAddress((void**)&fs,     g_fs);
    cudaGetSymbolAddress((void**)&psum,   g_psum);
    cudaGetSymbolAddress((void**)&inv,    g_inv);
    cudaGetSymbolAddress((void**)&yT,     g_yT);
    cudaGetSymbolAddress((void**)&z,      g_z);
    cudaGetSymbolAddress((void**)&bns,    g_bns);
    cudaGetSymbolAddress((void**)&bnq,    g_bnq);
    cudaGetSymbolAddress((void**)&wwz,    g_wwz);

    cudaFuncSetAttribute((const void*)proj_gemm, cudaFuncAttributeMaxDynamicSharedMemorySize, SM_BYTES);
    cudaFuncSetAttribute((const void*)mma_gemm<0,1,0,0>, cudaFuncAttributeMaxDynamicSharedMemorySize, SM_BYTES);
    cudaFuncSetAttribute((const void*)mma_gemm<0,0,1,0>, cudaFuncAttributeMaxDynamicSharedMemorySize, SM_BYTES);
    cudaFuncSetAttribute((const void*)mma_gemm<1,0,0,1>, cudaFuncAttributeMaxDynamicSharedMemorySize, SM_BYTES);

    dim3 blk(256);
    dim3 mblk(128);

    wsplit_all_kernel<<<2048, blk>>>(theta_w, phi_w, g_w, wz_w);
    transpose_split_kernel<<<dim3(LQ / 32, CFULL / 32, BATCH), blk>>>(x);

    // theta + phi + g in ONE launch (1536 CTAs)
    proj_gemm<<<dim3(192, BATCH), mblk, SM_BYTES>>>(theta_b, phi_b, g_b);

    // fs = exp(thetaT * phiP^T) split bf16, plus partial row sums
    mma_gemm<0,1,0,0><<<dim3(16, 32, BATCH), mblk, SM_BYTES>>>(
        thetaT, phiPT, nullptr, nullptr, psum, nullptr, fs, 256, 512, 512, 4096, 2048,
        (long)LQ * 512, (long)LK * 512, (long)LQ * 4096);

    rowsum_inv_kernel<<<BATCH * LQ / 8, blk>>>();

    // yT[L,Ci] split = (fs_split * gP_split^T) * inv[row]  (3 terms)
    mma_gemm<0,0,1,0><<<dim3(2, 32, BATCH), mblk, SM_BYTES>>>(
        fs, gP, nullptr, inv, nullptr, nullptr, yT, 2048, 4096, 4096, 512, 256,
        (long)LQ * 4096, (long)CI * 4096, (long)LQ * 512);

    // z[C,L] fp32 = wz_w * yT^T  (+bias m), with fused BN partial stats
    mma_gemm<1,0,0,1><<<dim3(32, 4, BATCH), mblk, SM_BYTES>>>(
        wwz, yT, wz_b, nullptr, bns, bnq, z, 256, 512, 512, LQ, 0,
        0L, (long)LQ * 512, (long)CFULL * LQ);

    bn_reduce_kernel<<<CFULL, blk>>>();
    bn_apply_kernel<<<(BATCH * CFULL * LQ) / (256 * 4), blk>>>(x, gamma, beta, out);
}